// round 10
// baseline (speedup 1.0000x reference)
#include <cuda_runtime.h>
#include <cuda_bf16.h>
#include <cstdint>

// Problem constants
#define C_IN   128
#define OC     768            // 512 qk-interleaved + 256 v
#define NP     36864          // 192*192 pixels
#define HH     192
#define WW     192
#define NHEAD  8

// Scratch
__device__ float g_v[(size_t)256 * NP];      // v [ch][pixel]
__device__ float g_t[(size_t)NHEAD * NP];    // scores
__device__ __align__(16) unsigned short gWhi[(size_t)OC * C_IN];   // bf16 bits, [o][c], head-interleaved qk
__device__ __align__(16) unsigned short gWlo[(size_t)OC * C_IN];
__device__ __align__(16) unsigned short gXhi[(size_t)NP * C_IN];   // bf16 bits, [p][c]
__device__ __align__(16) unsigned short gXlo[(size_t)NP * C_IN];

// ---------------------------------------------------------------------------
__device__ __forceinline__ void bf16_split(float f, unsigned short& h, unsigned short& l)
{
    __nv_bfloat16 hb = __float2bfloat16(f);
    float r = f - __bfloat162float(hb);
    __nv_bfloat16 lb = __float2bfloat16(r);
    h = __bfloat16_as_ushort(hb);
    l = __bfloat16_as_ushort(lb);
}

__device__ __forceinline__ void mma16816(float c[4],
                                         uint32_t a0, uint32_t a1, uint32_t a2, uint32_t a3,
                                         uint32_t b0, uint32_t b1)
{
    asm volatile(
        "mma.sync.aligned.m16n8k16.row.col.f32.bf16.bf16.f32 "
        "{%0,%1,%2,%3}, {%4,%5,%6,%7}, {%8,%9}, {%0,%1,%2,%3};\n"
        : "+f"(c[0]), "+f"(c[1]), "+f"(c[2]), "+f"(c[3])
        : "r"(a0), "r"(a1), "r"(a2), "r"(a3), "r"(b0), "r"(b1));
}

__device__ __forceinline__ void ldsm_x4(uint32_t& r0, uint32_t& r1, uint32_t& r2, uint32_t& r3,
                                        uint32_t saddr)
{
    asm volatile("ldmatrix.sync.aligned.m8n8.x4.shared.b16 {%0,%1,%2,%3}, [%4];"
                 : "=r"(r0), "=r"(r1), "=r"(r2), "=r"(r3) : "r"(saddr));
}

__device__ __forceinline__ void ldsm_x2(uint32_t& r0, uint32_t& r1, uint32_t saddr)
{
    asm volatile("ldmatrix.sync.aligned.m8n8.x2.shared.b16 {%0,%1}, [%2];"
                 : "=r"(r0), "=r"(r1) : "r"(saddr));
}

__device__ __forceinline__ void cpa16(uint32_t saddr, const void* g)
{
    asm volatile("cp.async.cg.shared.global [%0], [%1], 16;" :: "r"(saddr), "l"(g));
}

// ---------------------------------------------------------------------------
// Pre-pass A: convert W to bf16 hi/lo with head-interleaved q/k layout:
// rows [0,512): block of 64 per head = [wq head rows 0..31 | wk head rows 0..31]
// rows [512,768): wv. grid 96 x 256.
// ---------------------------------------------------------------------------
__global__ __launch_bounds__(256) void conv_w(
    const float* __restrict__ wq, const float* __restrict__ wk, const float* __restrict__ wv)
{
    int idx = (blockIdx.x * 256 + threadIdx.x) * 4;
    int row = idx >> 7, col = idx & 127;
    const float* src;
    if (row < 512) {
        int head = row >> 6, sub = row & 63;
        src = (sub < 32) ? (wq + (size_t)(head * 32 + sub) * 128)
                         : (wk + (size_t)(head * 32 + sub - 32) * 128);
    } else {
        src = wv + (size_t)(row - 512) * 128;
    }
    float4 v = *(const float4*)(src + col);
    unsigned short h[4], l[4];
    bf16_split(v.x, h[0], l[0]); bf16_split(v.y, h[1], l[1]);
    bf16_split(v.z, h[2], l[2]); bf16_split(v.w, h[3], l[3]);
    *(uint2*)(gWhi + idx) = make_uint2((uint32_t)h[0] | ((uint32_t)h[1] << 16),
                                       (uint32_t)h[2] | ((uint32_t)h[3] << 16));
    *(uint2*)(gWlo + idx) = make_uint2((uint32_t)l[0] | ((uint32_t)l[1] << 16),
                                       (uint32_t)l[2] | ((uint32_t)l[3] << 16));
}

// ---------------------------------------------------------------------------
// Pre-pass B: transpose+convert x [c][p] -> gX[p][c] bf16 hi/lo.
// ---------------------------------------------------------------------------
__global__ __launch_bounds__(256) void conv_x(const float* __restrict__ x)
{
    __shared__ float s[128][33];
    const int p0  = blockIdx.x * 32;
    const int tid = threadIdx.x;
    const int pr  = tid & 31, cr = tid >> 5;
#pragma unroll
    for (int l = 0; l < 16; l++) {
        int c = cr + l * 8;
        s[c][pr] = x[(size_t)c * NP + p0 + pr];
    }
    __syncthreads();
    const int p = tid >> 3, kq = tid & 7;
    __align__(16) unsigned short hv[16], lv[16];
#pragma unroll
    for (int i = 0; i < 16; i++)
        bf16_split(s[kq * 16 + i][p], hv[i], lv[i]);
    size_t base = (size_t)(p0 + p) * 128 + kq * 16;
    *(uint4*)(gXhi + base)     = ((const uint4*)hv)[0];
    *(uint4*)(gXhi + base + 8) = ((const uint4*)hv)[1];
    *(uint4*)(gXlo + base)     = ((const uint4*)lv)[0];
    *(uint4*)(gXlo + base + 8) = ((const uint4*)lv)[1];
}

// ---------------------------------------------------------------------------
// Kernel 1: QKV projection GEMM + fused q.k epilogue.
// CTA 128(o) x 128(p). bo<4: q/k heads (2 per CTA) -> write t only.
// bo in {4,5}: v -> write g_v. Double-buffered cp.async, smem 80 KB.
// ---------------------------------------------------------------------------
#define ROWS   80
#define ASTAGE 40960

__global__ __launch_bounds__(256, 2) void gemm_qkv()
{
    extern __shared__ unsigned char dsm[];
    const uint32_t sbase = (uint32_t)__cvta_generic_to_shared(dsm);

    const int bp   = blockIdx.x;
    const int bo   = blockIdx.y;
    const int tid  = threadIdx.x;
    const int wid  = tid >> 5;
    const int lane = tid & 31;
    const int warp_m = wid >> 2;
    const int warp_n = wid & 3;

    const int lrow0 = tid >> 2, lseg0 = tid & 3;
    const int lrow1 = (tid + 256) >> 2, lseg1 = tid & 3;

    const int a_mat  = lane >> 3;
    const int a_rowl = ((a_mat & 1) << 3) + (lane & 7);
    const int a_seg  = a_mat >> 1;
    const uint32_t aOff = (uint32_t)(warp_m * 64 + a_rowl) * ROWS + a_seg * 16;
    const int b_rowl = lane & 7;
    const int b_seg  = (lane >> 3) & 1;
    const uint32_t bOff = (uint32_t)(warp_n * 32 + b_rowl) * ROWS + b_seg * 16;

    float acc[4][4][4];
#pragma unroll
    for (int i = 0; i < 4; i++)
#pragma unroll
        for (int j = 0; j < 4; j++)
#pragma unroll
            for (int r = 0; r < 4; r++) acc[i][j][r] = 0.f;

    auto issue = [&](int kc, int st) {
        const uint32_t s0 = sbase + st * ASTAGE;
        {
            size_t gb0 = ((size_t)(bo * 128 + lrow0) * 128 + kc * 32);
            size_t gb1 = ((size_t)(bo * 128 + lrow1) * 128 + kc * 32);
            cpa16(s0 + lrow0 * ROWS + lseg0 * 16,         gWhi + gb0 + lseg0 * 8);
            cpa16(s0 + lrow1 * ROWS + lseg1 * 16,         gWhi + gb1 + lseg1 * 8);
            cpa16(s0 + 10240 + lrow0 * ROWS + lseg0 * 16, gWlo + gb0 + lseg0 * 8);
            cpa16(s0 + 10240 + lrow1 * ROWS + lseg1 * 16, gWlo + gb1 + lseg1 * 8);
        }
        {
            size_t gb0 = ((size_t)(bp * 128 + lrow0) * 128 + kc * 32);
            size_t gb1 = ((size_t)(bp * 128 + lrow1) * 128 + kc * 32);
            cpa16(s0 + 20480 + lrow0 * ROWS + lseg0 * 16, gXhi + gb0 + lseg0 * 8);
            cpa16(s0 + 20480 + lrow1 * ROWS + lseg1 * 16, gXhi + gb1 + lseg1 * 8);
            cpa16(s0 + 30720 + lrow0 * ROWS + lseg0 * 16, gXlo + gb0 + lseg0 * 8);
            cpa16(s0 + 30720 + lrow1 * ROWS + lseg1 * 16, gXlo + gb1 + lseg1 * 8);
        }
    };

    issue(0, 0);
    asm volatile("cp.async.commit_group;");

    for (int kc = 0; kc < 4; kc++) {
        const int st = kc & 1;
        if (kc < 3) issue(kc + 1, st ^ 1);
        asm volatile("cp.async.commit_group;");
        if (kc < 3) asm volatile("cp.async.wait_group 1;");
        else        asm volatile("cp.async.wait_group 0;");
        __syncthreads();

        const uint32_t sAhi_b = sbase + st * ASTAGE;
        const uint32_t sAlo_b = sAhi_b + 10240;
        const uint32_t sBhi_b = sAhi_b + 20480;
        const uint32_t sBlo_b = sAhi_b + 30720;

#pragma unroll
        for (int ks = 0; ks < 2; ks++) {
            const int klb = ks * 32;
            uint32_t ahi[4][4], alo_[4][4];
#pragma unroll
            for (int i = 0; i < 4; i++) {
                uint32_t ao = aOff + klb + (uint32_t)i * 16 * ROWS;
                ldsm_x4(ahi[i][0], ahi[i][1], ahi[i][2], ahi[i][3], sAhi_b + ao);
                ldsm_x4(alo_[i][0], alo_[i][1], alo_[i][2], alo_[i][3], sAlo_b + ao);
            }
#pragma unroll
            for (int j = 0; j < 4; j++) {
                uint32_t bo_ = bOff + klb + (uint32_t)j * 8 * ROWS;
                uint32_t bh0, bh1, bl0, bl1;
                ldsm_x2(bh0, bh1, sBhi_b + bo_);
                ldsm_x2(bl0, bl1, sBlo_b + bo_);
                // term-outer, i-inner: 4 independent accumulators between reuses
#pragma unroll
                for (int i = 0; i < 4; i++)
                    mma16816(acc[i][j], ahi[i][0], ahi[i][1], ahi[i][2], ahi[i][3], bh0, bh1);
#pragma unroll
                for (int i = 0; i < 4; i++)
                    mma16816(acc[i][j], ahi[i][0], ahi[i][1], ahi[i][2], ahi[i][3], bl0, bl1);
#pragma unroll
                for (int i = 0; i < 4; i++)
                    mma16816(acc[i][j], alo_[i][0], alo_[i][1], alo_[i][2], alo_[i][3], bh0, bh1);
            }
        }
        __syncthreads();
    }

    const int g = lane >> 2;
    const int q = lane & 3;

    if (bo < 4) {
        // ---- fused q.k epilogue: warp_m's 64 rows = [32 q | 32 k] of one head.
        const int head = bo * 2 + warp_m;
        float* tb = g_t + (size_t)head * NP;
#pragma unroll
        for (int j = 0; j < 4; j++) {
            float s0 = 0.f, s1 = 0.f;
#pragma unroll
            for (int i = 0; i < 2; i++) {
                s0 += acc[i][j][0] * acc[i + 2][j][0] + acc[i][j][2] * acc[i + 2][j][2];
                s1 += acc[i][j][1] * acc[i + 2][j][1] + acc[i][j][3] * acc[i + 2][j][3];
            }
#pragma unroll
            for (int m = 4; m <= 16; m <<= 1) {
                s0 += __shfl_xor_sync(0xffffffffu, s0, m);
                s1 += __shfl_xor_sync(0xffffffffu, s1, m);
            }
            if (g == 0) {
                int p = bp * 128 + warp_n * 32 + j * 8 + 2 * q;
                *(float2*)(tb + p) = make_float2(s0 * 0.0625f, s1 * 0.0625f);
            }
        }
    } else {
        // ---- v epilogue ----
#pragma unroll
        for (int i = 0; i < 4; i++) {
            int o = (bo - 4) * 128 + warp_m * 64 + i * 16 + g;
#pragma unroll
            for (int j = 0; j < 4; j++) {
                int p = bp * 128 + warp_n * 32 + j * 8 + 2 * q;
                *(float2*)(g_v + (size_t)o * NP + p)       = make_float2(acc[i][j][0], acc[i][j][1]);
                *(float2*)(g_v + (size_t)(o + 8) * NP + p) = make_float2(acc[i][j][2], acc[i][j][3]);
            }
        }
    }
}

// ---------------------------------------------------------------------------
// Kernel 3: 3x3 regional softmax + weighted V sum.
// grid (192, 16): block = row h, head (y>>1), 16-channel half (y&1).
// Phase 1: softmax weights for this head's 192 w positions (smem).
// Phase 2: dh-outer, 4-channel inner. Halo (left/right) values come from
// neighbor lanes via shfl (adjacent quads live in adjacent lanes within the
// same 48-quad channel segment); only warp-boundary lanes fall back to LDG.
// OOB slots contribute score 0 (exp(0-m)); OOB v contributes 0.
// ---------------------------------------------------------------------------
__global__ __launch_bounds__(192, 7) void attn(float* __restrict__ out)
{
    __shared__ float w9s[9][192];

    const int h    = blockIdx.x;        // 0..191
    const int head = blockIdx.y >> 1;   // 0..7
    const int chf  = blockIdx.y & 1;    // 0..1 channel half
    const int tid  = threadIdx.x;       // 0..191
    const int lane = tid & 31;

    // ---- phase 1: softmax weights for (h, head) ----
    {
        const int w = tid;
        const float* tb = g_t + (size_t)head * NP;
        float sc[9];
#pragma unroll
        for (int s = 0; s < 9; s++) {
            int hh = h + s / 3 - 1;
            int ww = w + s % 3 - 1;
            float v = 0.f;
            if ((unsigned)hh < 192u && (unsigned)ww < 192u)
                v = tb[hh * WW + ww];
            sc[s] = v;
        }
        float m = sc[0];
#pragma unroll
        for (int s = 1; s < 9; s++) m = fmaxf(m, sc[s]);
        float sum = 0.f;
#pragma unroll
        for (int s = 0; s < 9; s++) { float e = __expf(sc[s] - m); sc[s] = e; sum += e; }
        float inv = 1.0f / sum;
#pragma unroll
        for (int s = 0; s < 9; s++) w9s[s][w] = sc[s] * inv;
    }
    __syncthreads();

    // ---- phase 2 ----
    const int qw  = tid % 48;                       // w-quad index
    const int w0  = qw * 4;
    const int cl4 = tid / 48;                       // 0..3
    const int ch0 = head * 32 + chf * 16 + cl4;     // channels ch0 + {0,4,8,12}

    // halo sourcing: shfl when neighbor quad is in-warp & same channel segment
    const bool left_zero  = (qw == 0);
    const bool right_zero = (qw == 47);
    const bool left_shfl  = (!left_zero)  && (lane != 0);
    const bool right_shfl = (!right_zero) && (lane != 31);

    float o[4][4];
#pragma unroll
    for (int c = 0; c < 4; c++)
#pragma unroll
        for (int r = 0; r < 4; r++) o[c][r] = 0.f;

    const float* vbase = g_v + (size_t)ch0 * NP + w0;

#pragma unroll
    for (int dh = 0; dh < 3; dh++) {
        int hh = h + dh - 1;
        if ((unsigned)hh >= 192u) continue;

        float4 Wa = *(const float4*)&w9s[dh * 3 + 0][w0];
        float4 Wb = *(const float4*)&w9s[dh * 3 + 1][w0];
        float4 Wc = *(const float4*)&w9s[dh * 3 + 2][w0];

        const float* rb = vbase + hh * WW;
#pragma unroll
        for (int co = 0; co < 4; co++) {
            const float* row = rb + (size_t)(co * 4) * NP;
            float4 c = *(const float4*)row;

            float lsh = __shfl_up_sync(0xffffffffu, c.w, 1);
            float rsh = __shfl_down_sync(0xffffffffu, c.x, 1);

            float left  = left_zero  ? 0.f : (left_shfl  ? lsh : row[-1]);
            float right = right_zero ? 0.f : (right_shfl ? rsh : row[4]);

            o[co][0] += Wa.x * left + Wb.x * c.x + Wc.x * c.y;
            o[co][1] += Wa.y * c.x  + Wb.y * c.y + Wc.y * c.z;
            o[co][2] += Wa.z * c.y  + Wb.z * c.z + Wc.z * c.w;
            o[co][3] += Wa.w * c.z  + Wb.w * c.w + Wc.w * right;
        }
    }

    float* ob = out + (size_t)ch0 * NP + h * WW + w0;
#pragma unroll
    for (int co = 0; co < 4; co++)
        *(float4*)(ob + (size_t)(co * 4) * NP) = make_float4(o[co][0], o[co][1], o[co][2], o[co][3]);
}

// ---------------------------------------------------------------------------
extern "C" void kernel_launch(void* const* d_in, const int* in_sizes, int n_in,
                              void* d_out, int out_size)
{
    const float* x  = (const float*)d_in[0];
    const float* wq = (const float*)d_in[1];
    const float* wk = (const float*)d_in[2];
    const float* wv = (const float*)d_in[3];
    float* out = (float*)d_out;

    cudaFuncSetAttribute(gemm_qkv, cudaFuncAttributeMaxDynamicSharedMemorySize, 2 * ASTAGE);

    conv_w<<<96, 256>>>(wq, wk, wv);
    conv_x<<<NP / 32, 256>>>(x);

    dim3 g1(NP / 128, OC / 128);     // (288, 6)
    gemm_qkv<<<g1, 256, 2 * ASTAGE>>>();

    dim3 g3(HH, 16);                 // (192, 16)
    attn<<<g3, 192>>>(out);
}

// round 11
// speedup vs baseline: 1.0630x; 1.0630x over previous
#include <cuda_runtime.h>
#include <cuda_bf16.h>
#include <cstdint>

// Problem constants
#define C_IN   128
#define OC     768            // 512 qk-interleaved + 256 v
#define NP     36864          // 192*192 pixels
#define HH     192
#define WW     192
#define NHEAD  8

// Scratch
__device__ float g_v[(size_t)256 * NP];      // v [ch][pixel]
__device__ float g_t[(size_t)NHEAD * NP];    // scores
__device__ __align__(16) unsigned short gWhi[(size_t)OC * C_IN];   // bf16 bits, [o][c], head-interleaved qk
__device__ __align__(16) unsigned short gWlo[(size_t)OC * C_IN];
__device__ __align__(16) unsigned short gXhi[(size_t)NP * C_IN];   // bf16 bits, [p][c]
__device__ __align__(16) unsigned short gXlo[(size_t)NP * C_IN];

// ---------------------------------------------------------------------------
__device__ __forceinline__ void bf16_split(float f, unsigned short& h, unsigned short& l)
{
    __nv_bfloat16 hb = __float2bfloat16(f);
    float r = f - __bfloat162float(hb);
    __nv_bfloat16 lb = __float2bfloat16(r);
    h = __bfloat16_as_ushort(hb);
    l = __bfloat16_as_ushort(lb);
}

__device__ __forceinline__ void mma16816(float c[4],
                                         uint32_t a0, uint32_t a1, uint32_t a2, uint32_t a3,
                                         uint32_t b0, uint32_t b1)
{
    asm volatile(
        "mma.sync.aligned.m16n8k16.row.col.f32.bf16.bf16.f32 "
        "{%0,%1,%2,%3}, {%4,%5,%6,%7}, {%8,%9}, {%0,%1,%2,%3};\n"
        : "+f"(c[0]), "+f"(c[1]), "+f"(c[2]), "+f"(c[3])
        : "r"(a0), "r"(a1), "r"(a2), "r"(a3), "r"(b0), "r"(b1));
}

__device__ __forceinline__ void ldsm_x4(uint32_t& r0, uint32_t& r1, uint32_t& r2, uint32_t& r3,
                                        uint32_t saddr)
{
    asm volatile("ldmatrix.sync.aligned.m8n8.x4.shared.b16 {%0,%1,%2,%3}, [%4];"
                 : "=r"(r0), "=r"(r1), "=r"(r2), "=r"(r3) : "r"(saddr));
}

__device__ __forceinline__ void ldsm_x2(uint32_t& r0, uint32_t& r1, uint32_t saddr)
{
    asm volatile("ldmatrix.sync.aligned.m8n8.x2.shared.b16 {%0,%1}, [%2];"
                 : "=r"(r0), "=r"(r1) : "r"(saddr));
}

__device__ __forceinline__ void cpa16(uint32_t saddr, const void* g)
{
    asm volatile("cp.async.cg.shared.global [%0], [%1], 16;" :: "r"(saddr), "l"(g));
}

// ---------------------------------------------------------------------------
// Pre-pass A: convert W to bf16 hi/lo with head-interleaved q/k layout:
// rows [0,512): block of 64 per head = [wq head rows 0..31 | wk head rows 0..31]
// rows [512,768): wv. grid 96 x 256.
// ---------------------------------------------------------------------------
__global__ __launch_bounds__(256) void conv_w(
    const float* __restrict__ wq, const float* __restrict__ wk, const float* __restrict__ wv)
{
    int idx = (blockIdx.x * 256 + threadIdx.x) * 4;
    int row = idx >> 7, col = idx & 127;
    const float* src;
    if (row < 512) {
        int head = row >> 6, sub = row & 63;
        src = (sub < 32) ? (wq + (size_t)(head * 32 + sub) * 128)
                         : (wk + (size_t)(head * 32 + sub - 32) * 128);
    } else {
        src = wv + (size_t)(row - 512) * 128;
    }
    float4 v = *(const float4*)(src + col);
    unsigned short h[4], l[4];
    bf16_split(v.x, h[0], l[0]); bf16_split(v.y, h[1], l[1]);
    bf16_split(v.z, h[2], l[2]); bf16_split(v.w, h[3], l[3]);
    *(uint2*)(gWhi + idx) = make_uint2((uint32_t)h[0] | ((uint32_t)h[1] << 16),
                                       (uint32_t)h[2] | ((uint32_t)h[3] << 16));
    *(uint2*)(gWlo + idx) = make_uint2((uint32_t)l[0] | ((uint32_t)l[1] << 16),
                                       (uint32_t)l[2] | ((uint32_t)l[3] << 16));
}

// ---------------------------------------------------------------------------
// Pre-pass B: transpose+convert x [c][p] -> gX[p][c] bf16 hi/lo.
// ---------------------------------------------------------------------------
__global__ __launch_bounds__(256) void conv_x(const float* __restrict__ x)
{
    __shared__ float s[128][33];
    const int p0  = blockIdx.x * 32;
    const int tid = threadIdx.x;
    const int pr  = tid & 31, cr = tid >> 5;
#pragma unroll
    for (int l = 0; l < 16; l++) {
        int c = cr + l * 8;
        s[c][pr] = x[(size_t)c * NP + p0 + pr];
    }
    __syncthreads();
    const int p = tid >> 3, kq = tid & 7;
    __align__(16) unsigned short hv[16], lv[16];
#pragma unroll
    for (int i = 0; i < 16; i++)
        bf16_split(s[kq * 16 + i][p], hv[i], lv[i]);
    size_t base = (size_t)(p0 + p) * 128 + kq * 16;
    *(uint4*)(gXhi + base)     = ((const uint4*)hv)[0];
    *(uint4*)(gXhi + base + 8) = ((const uint4*)hv)[1];
    *(uint4*)(gXlo + base)     = ((const uint4*)lv)[0];
    *(uint4*)(gXlo + base + 8) = ((const uint4*)lv)[1];
}

// ---------------------------------------------------------------------------
// Kernel 1: QKV projection GEMM + fused q.k epilogue.
// CTA 128(o) x 128(p). bo<4: q/k heads (2 per CTA) -> write t only.
// bo in {4,5}: v -> write g_v. Double-buffered cp.async, smem 80 KB.
// ---------------------------------------------------------------------------
#define ROWS   80
#define ASTAGE 40960

__global__ __launch_bounds__(256, 2) void gemm_qkv()
{
    extern __shared__ unsigned char dsm[];
    const uint32_t sbase = (uint32_t)__cvta_generic_to_shared(dsm);

    const int bp   = blockIdx.x;
    const int bo   = blockIdx.y;
    const int tid  = threadIdx.x;
    const int wid  = tid >> 5;
    const int lane = tid & 31;
    const int warp_m = wid >> 2;
    const int warp_n = wid & 3;

    const int lrow0 = tid >> 2, lseg0 = tid & 3;
    const int lrow1 = (tid + 256) >> 2, lseg1 = tid & 3;

    const int a_mat  = lane >> 3;
    const int a_rowl = ((a_mat & 1) << 3) + (lane & 7);
    const int a_seg  = a_mat >> 1;
    const uint32_t aOff = (uint32_t)(warp_m * 64 + a_rowl) * ROWS + a_seg * 16;
    const int b_rowl = lane & 7;
    const int b_seg  = (lane >> 3) & 1;
    const uint32_t bOff = (uint32_t)(warp_n * 32 + b_rowl) * ROWS + b_seg * 16;

    float acc[4][4][4];
#pragma unroll
    for (int i = 0; i < 4; i++)
#pragma unroll
        for (int j = 0; j < 4; j++)
#pragma unroll
            for (int r = 0; r < 4; r++) acc[i][j][r] = 0.f;

    auto issue = [&](int kc, int st) {
        const uint32_t s0 = sbase + st * ASTAGE;
        {
            size_t gb0 = ((size_t)(bo * 128 + lrow0) * 128 + kc * 32);
            size_t gb1 = ((size_t)(bo * 128 + lrow1) * 128 + kc * 32);
            cpa16(s0 + lrow0 * ROWS + lseg0 * 16,         gWhi + gb0 + lseg0 * 8);
            cpa16(s0 + lrow1 * ROWS + lseg1 * 16,         gWhi + gb1 + lseg1 * 8);
            cpa16(s0 + 10240 + lrow0 * ROWS + lseg0 * 16, gWlo + gb0 + lseg0 * 8);
            cpa16(s0 + 10240 + lrow1 * ROWS + lseg1 * 16, gWlo + gb1 + lseg1 * 8);
        }
        {
            size_t gb0 = ((size_t)(bp * 128 + lrow0) * 128 + kc * 32);
            size_t gb1 = ((size_t)(bp * 128 + lrow1) * 128 + kc * 32);
            cpa16(s0 + 20480 + lrow0 * ROWS + lseg0 * 16, gXhi + gb0 + lseg0 * 8);
            cpa16(s0 + 20480 + lrow1 * ROWS + lseg1 * 16, gXhi + gb1 + lseg1 * 8);
            cpa16(s0 + 30720 + lrow0 * ROWS + lseg0 * 16, gXlo + gb0 + lseg0 * 8);
            cpa16(s0 + 30720 + lrow1 * ROWS + lseg1 * 16, gXlo + gb1 + lseg1 * 8);
        }
    };

    issue(0, 0);
    asm volatile("cp.async.commit_group;");

    for (int kc = 0; kc < 4; kc++) {
        const int st = kc & 1;
        if (kc < 3) issue(kc + 1, st ^ 1);
        asm volatile("cp.async.commit_group;");
        if (kc < 3) asm volatile("cp.async.wait_group 1;");
        else        asm volatile("cp.async.wait_group 0;");
        __syncthreads();

        const uint32_t sAhi_b = sbase + st * ASTAGE;
        const uint32_t sAlo_b = sAhi_b + 10240;
        const uint32_t sBhi_b = sAhi_b + 20480;
        const uint32_t sBlo_b = sAhi_b + 30720;

#pragma unroll
        for (int ks = 0; ks < 2; ks++) {
            const int klb = ks * 32;
            uint32_t ahi[4][4], alo_[4][4];
#pragma unroll
            for (int i = 0; i < 4; i++) {
                uint32_t ao = aOff + klb + (uint32_t)i * 16 * ROWS;
                ldsm_x4(ahi[i][0], ahi[i][1], ahi[i][2], ahi[i][3], sAhi_b + ao);
                ldsm_x4(alo_[i][0], alo_[i][1], alo_[i][2], alo_[i][3], sAlo_b + ao);
            }
#pragma unroll
            for (int j = 0; j < 4; j++) {
                uint32_t bo_ = bOff + klb + (uint32_t)j * 8 * ROWS;
                uint32_t bh0, bh1, bl0, bl1;
                ldsm_x2(bh0, bh1, sBhi_b + bo_);
                ldsm_x2(bl0, bl1, sBlo_b + bo_);
                // term-outer, i-inner: 4 independent accumulators between reuses
#pragma unroll
                for (int i = 0; i < 4; i++)
                    mma16816(acc[i][j], ahi[i][0], ahi[i][1], ahi[i][2], ahi[i][3], bh0, bh1);
#pragma unroll
                for (int i = 0; i < 4; i++)
                    mma16816(acc[i][j], ahi[i][0], ahi[i][1], ahi[i][2], ahi[i][3], bl0, bl1);
#pragma unroll
                for (int i = 0; i < 4; i++)
                    mma16816(acc[i][j], alo_[i][0], alo_[i][1], alo_[i][2], alo_[i][3], bh0, bh1);
            }
        }
        __syncthreads();
    }

    const int g = lane >> 2;
    const int q = lane & 3;

    if (bo < 4) {
        // ---- fused q.k epilogue: warp_m's 64 rows = [32 q | 32 k] of one head.
        const int head = bo * 2 + warp_m;
        float* tb = g_t + (size_t)head * NP;
#pragma unroll
        for (int j = 0; j < 4; j++) {
            float s0 = 0.f, s1 = 0.f;
#pragma unroll
            for (int i = 0; i < 2; i++) {
                s0 += acc[i][j][0] * acc[i + 2][j][0] + acc[i][j][2] * acc[i + 2][j][2];
                s1 += acc[i][j][1] * acc[i + 2][j][1] + acc[i][j][3] * acc[i + 2][j][3];
            }
#pragma unroll
            for (int m = 4; m <= 16; m <<= 1) {
                s0 += __shfl_xor_sync(0xffffffffu, s0, m);
                s1 += __shfl_xor_sync(0xffffffffu, s1, m);
            }
            if (g == 0) {
                int p = bp * 128 + warp_n * 32 + j * 8 + 2 * q;
                *(float2*)(tb + p) = make_float2(s0 * 0.0625f, s1 * 0.0625f);
            }
        }
    } else {
        // ---- v epilogue ----
#pragma unroll
        for (int i = 0; i < 4; i++) {
            int o = (bo - 4) * 128 + warp_m * 64 + i * 16 + g;
#pragma unroll
            for (int j = 0; j < 4; j++) {
                int p = bp * 128 + warp_n * 32 + j * 8 + 2 * q;
                *(float2*)(g_v + (size_t)o * NP + p)       = make_float2(acc[i][j][0], acc[i][j][1]);
                *(float2*)(g_v + (size_t)(o + 8) * NP + p) = make_float2(acc[i][j][2], acc[i][j][3]);
            }
        }
    }
}

// ---------------------------------------------------------------------------
// Kernel 3: 3x3 regional softmax + weighted V sum, 2 output rows per block.
// grid (96, 16): block = rows {h0, h0+1}, head (y>>1), 16-ch half (y&1).
// 384 threads. Phase 1: weights for both rows (tid = r*192 + w).
// Phase 2: walk 4 input rows ONCE; each feeds the 1-2 output rows in range.
// Thread = (w-quad 0..47, ch-sub 0..7) handling channels {cl, cl+8}.
// OOB slots contribute score 0 (exp(0-m)); OOB v contributes 0.
// ---------------------------------------------------------------------------
__global__ __launch_bounds__(384, 3) void attn(float* __restrict__ out)
{
    __shared__ float w9s[2][9][192];

    const int h0   = blockIdx.x * 2;    // first output row
    const int head = blockIdx.y >> 1;   // 0..7
    const int chf  = blockIdx.y & 1;    // 0..1 channel half
    const int tid  = threadIdx.x;       // 0..383

    // ---- phase 1: softmax weights for rows h0, h0+1 ----
    {
        const int r = tid / 192;        // 0..1
        const int w = tid % 192;
        const int h = h0 + r;
        const float* tb = g_t + (size_t)head * NP;
        float sc[9];
#pragma unroll
        for (int s = 0; s < 9; s++) {
            int hh = h + s / 3 - 1;
            int ww = w + s % 3 - 1;
            float v = 0.f;
            if ((unsigned)hh < 192u && (unsigned)ww < 192u)
                v = tb[hh * WW + ww];
            sc[s] = v;
        }
        float m = sc[0];
#pragma unroll
        for (int s = 1; s < 9; s++) m = fmaxf(m, sc[s]);
        float sum = 0.f;
#pragma unroll
        for (int s = 0; s < 9; s++) { float e = __expf(sc[s] - m); sc[s] = e; sum += e; }
        float inv = 1.0f / sum;
#pragma unroll
        for (int s = 0; s < 9; s++) w9s[r][s][w] = sc[s] * inv;
    }
    __syncthreads();

    // ---- phase 2 ----
    const int qw = tid % 48;
    const int w0 = qw * 4;
    const int cl = tid / 48;                        // 0..7
    const int ch0 = head * 32 + chf * 16 + cl;      // channels ch0, ch0+8

    float o[2][2][4];
#pragma unroll
    for (int r = 0; r < 2; r++)
#pragma unroll
        for (int c = 0; c < 2; c++)
#pragma unroll
            for (int k = 0; k < 4; k++) o[r][c][k] = 0.f;

    const float* vb0 = g_v + (size_t)ch0 * NP + w0;
    const float* vb1 = vb0 + (size_t)8 * NP;

#pragma unroll
    for (int hi = 0; hi < 4; hi++) {
        const int hh = h0 - 1 + hi;
        if ((unsigned)hh >= 192u) continue;

        const float* row0 = vb0 + hh * WW;
        const float* row1 = vb1 + hh * WW;
        float4 c0 = *(const float4*)row0;
        float4 c1 = *(const float4*)row1;
        float l0 = (w0 > 0)   ? row0[-1] : 0.f;
        float r0 = (w0 < 188) ? row0[4]  : 0.f;
        float l1 = (w0 > 0)   ? row1[-1] : 0.f;
        float r1 = (w0 < 188) ? row1[4]  : 0.f;

#pragma unroll
        for (int r = 0; r < 2; r++) {
            const int dh = hi - r;                  // weight row for output h0+r
            if (dh < 0 || dh > 2) continue;
            float4 Wa = *(const float4*)&w9s[r][dh * 3 + 0][w0];
            float4 Wb = *(const float4*)&w9s[r][dh * 3 + 1][w0];
            float4 Wc = *(const float4*)&w9s[r][dh * 3 + 2][w0];

            o[r][0][0] += Wa.x * l0   + Wb.x * c0.x + Wc.x * c0.y;
            o[r][0][1] += Wa.y * c0.x + Wb.y * c0.y + Wc.y * c0.z;
            o[r][0][2] += Wa.z * c0.y + Wb.z * c0.z + Wc.z * c0.w;
            o[r][0][3] += Wa.w * c0.z + Wb.w * c0.w + Wc.w * r0;

            o[r][1][0] += Wa.x * l1   + Wb.x * c1.x + Wc.x * c1.y;
            o[r][1][1] += Wa.y * c1.x + Wb.y * c1.y + Wc.y * c1.z;
            o[r][1][2] += Wa.z * c1.y + Wb.z * c1.z + Wc.z * c1.w;
            o[r][1][3] += Wa.w * c1.z + Wb.w * c1.w + Wc.w * r1;
        }
    }

#pragma unroll
    for (int r = 0; r < 2; r++) {
        float* ob0 = out + (size_t)ch0 * NP + (h0 + r) * WW + w0;
        *(float4*)ob0 = make_float4(o[r][0][0], o[r][0][1], o[r][0][2], o[r][0][3]);
        *(float4*)(ob0 + (size_t)8 * NP) = make_float4(o[r][1][0], o[r][1][1], o[r][1][2], o[r][1][3]);
    }
}

// ---------------------------------------------------------------------------
extern "C" void kernel_launch(void* const* d_in, const int* in_sizes, int n_in,
                              void* d_out, int out_size)
{
    const float* x  = (const float*)d_in[0];
    const float* wq = (const float*)d_in[1];
    const float* wk = (const float*)d_in[2];
    const float* wv = (const float*)d_in[3];
    float* out = (float*)d_out;

    cudaFuncSetAttribute(gemm_qkv, cudaFuncAttributeMaxDynamicSharedMemorySize, 2 * ASTAGE);

    conv_w<<<96, 256>>>(wq, wk, wv);
    conv_x<<<NP / 32, 256>>>(x);

    dim3 g1(NP / 128, OC / 128);     // (288, 6)
    gemm_qkv<<<g1, 256, 2 * ASTAGE>>>();

    dim3 g3(HH / 2, 16);             // (96, 16)
    attn<<<g3, 384>>>(out);
}

// round 12
// speedup vs baseline: 1.3913x; 1.3088x over previous
#include <cuda_runtime.h>
#include <cuda_bf16.h>
#include <cstdint>

// Problem constants
#define C_IN   128
#define NP     36864          // 192*192 pixels
#define HH     192
#define WW     192
#define NHEAD  8

// Scratch
__device__ float g_v[(size_t)256 * NP];      // v [ch][pixel]
__device__ float g_t[(size_t)NHEAD * NP];    // scores

// ---------------------------------------------------------------------------
__device__ __forceinline__ uint32_t f2tf32(float f)
{
    uint32_t r;
    asm("cvt.rna.tf32.f32 %0, %1;" : "=r"(r) : "f"(f));
    return r;
}

__device__ __forceinline__ void mma_tf32(float c[4],
                                         uint32_t a0, uint32_t a1, uint32_t a2, uint32_t a3,
                                         uint32_t b0, uint32_t b1)
{
    asm volatile(
        "mma.sync.aligned.m16n8k8.row.col.f32.tf32.tf32.f32 "
        "{%0,%1,%2,%3}, {%4,%5,%6,%7}, {%8,%9}, {%0,%1,%2,%3};\n"
        : "+f"(c[0]), "+f"(c[1]), "+f"(c[2]), "+f"(c[3])
        : "r"(a0), "r"(a1), "r"(a2), "r"(a3), "r"(b0), "r"(b1));
}

__device__ __forceinline__ void cpa16(uint32_t saddr, const void* g)
{
    asm volatile("cp.async.cg.shared.global [%0], [%1], 16;" :: "r"(saddr), "l"(g));
}

// ---------------------------------------------------------------------------
// Kernel 1: QKV projection GEMM (single-pass TF32) + fused q.k epilogue.
// CTA 128(o) x 128(p), K=128 in 4 chunks of 32, double-buffered cp.async
// STRAIGHT from the fp32 inputs (no pre-pass).
// Logical A rows: [0,512) = head-interleaved [32 q | 32 k] per head (virtual
// mapping to wq/wk rows at load time); [512,768) = wv rows.
// bo<4: q/k heads (2 per CTA) -> write t only. bo in {4,5}: v -> g_v.
//
// SMEM per stage: A [128 o][32 k] fp32, row stride 36 words (144 B);
//                 B [32 k][128 p] fp32, row stride 136 words (544 B).
// Fragment LDS patterns are bank-conflict-free (4m+k / 8k+n cover 0..31).
// ---------------------------------------------------------------------------
#define ARSW   36
#define BRSW   136
#define ABYTES (128 * ARSW * 4)            // 18432
#define BBYTES (32 * BRSW * 4)             // 17408
#define STAGE  (ABYTES + BBYTES)           // 35840

__global__ __launch_bounds__(256, 2) void gemm_qkv(
    const float* __restrict__ x,
    const float* __restrict__ wq,
    const float* __restrict__ wk,
    const float* __restrict__ wv)
{
    extern __shared__ unsigned char dsm[];
    const uint32_t sbase = (uint32_t)__cvta_generic_to_shared(dsm);

    const int bp   = blockIdx.x;
    const int bo   = blockIdx.y;
    const int tid  = threadIdx.x;
    const int wid  = tid >> 5;
    const int lane = tid & 31;
    const int warp_m = wid >> 2;
    const int warp_n = wid & 3;

    // ---- loader precompute: 4 A-chunks + 4 B-chunks of 16 B per thread ----
    const float* asrc[4]; uint32_t adst[4];
    const float* bsrc[4]; uint32_t bdst[4];
#pragma unroll
    for (int l = 0; l < 4; l++) {
        int c = tid + l * 256;             // 0..1023
        {   // A: row = c>>3 (0..127), seg = c&7 (16B units within 128B row)
            int row = c >> 3, seg = c & 7;
            int rg = bo * 128 + row;
            const float* srow;
            if (rg < 512) {
                int head = rg >> 6, sub = rg & 63;
                srow = (sub < 32) ? (wq + (size_t)(head * 32 + sub) * 128)
                                  : (wk + (size_t)(head * 32 + sub - 32) * 128);
            } else {
                srow = wv + (size_t)(rg - 512) * 128;
            }
            asrc[l] = srow + seg * 4;
            adst[l] = (uint32_t)(row * 144 + seg * 16);
        }
        {   // B: row = c>>5 (0..31 k), seg = c&31 (16B units within 512B row)
            int row = c >> 5, seg = c & 31;
            bsrc[l] = x + (size_t)row * NP + bp * 128 + seg * 4;
            bdst[l] = (uint32_t)(ABYTES + row * 544 + seg * 16);
        }
    }

    float acc[4][4][4];
#pragma unroll
    for (int i = 0; i < 4; i++)
#pragma unroll
        for (int j = 0; j < 4; j++)
#pragma unroll
            for (int r = 0; r < 4; r++) acc[i][j][r] = 0.f;

    auto issue = [&](int kc, int st) {
        const uint32_t s0 = sbase + st * STAGE;
#pragma unroll
        for (int l = 0; l < 4; l++)
            cpa16(s0 + adst[l], asrc[l] + kc * 32);
#pragma unroll
        for (int l = 0; l < 4; l++)
            cpa16(s0 + bdst[l], bsrc[l] + (size_t)(kc * 32) * NP);
    };

    issue(0, 0);
    asm volatile("cp.async.commit_group;");

    for (int kc = 0; kc < 4; kc++) {
        const int st = kc & 1;
        if (kc < 3) issue(kc + 1, st ^ 1);
        asm volatile("cp.async.commit_group;");
        if (kc < 3) asm volatile("cp.async.wait_group 1;");
        else        asm volatile("cp.async.wait_group 0;");
        __syncthreads();

        const float* fA = (const float*)(dsm + st * STAGE);
        const float* fB = (const float*)(dsm + st * STAGE + ABYTES);

#pragma unroll
        for (int ks = 0; ks < 4; ks++) {
            const int kw = ks * 8 + (lane & 3);     // k word within chunk

            uint32_t a[4][4];
#pragma unroll
            for (int i = 0; i < 4; i++) {
                int base = (warp_m * 64 + i * 16 + (lane >> 2)) * ARSW + kw;
                a[i][0] = f2tf32(fA[base]);
                a[i][1] = f2tf32(fA[base + 8 * ARSW]);
                a[i][2] = f2tf32(fA[base + 4]);
                a[i][3] = f2tf32(fA[base + 8 * ARSW + 4]);
            }
#pragma unroll
            for (int j = 0; j < 4; j++) {
                int bb = kw * BRSW + warp_n * 32 + j * 8 + (lane >> 2);
                uint32_t b0 = f2tf32(fB[bb]);
                uint32_t b1 = f2tf32(fB[bb + 4 * BRSW]);
#pragma unroll
                for (int i = 0; i < 4; i++)
                    mma_tf32(acc[i][j], a[i][0], a[i][1], a[i][2], a[i][3], b0, b1);
            }
        }
        __syncthreads();
    }

    const int g = lane >> 2;
    const int q = lane & 3;

    if (bo < 4) {
        // ---- fused q.k epilogue: warp_m's 64 rows = [32 q | 32 k] of one head.
        const int head = bo * 2 + warp_m;
        float* tb = g_t + (size_t)head * NP;
#pragma unroll
        for (int j = 0; j < 4; j++) {
            float s0 = 0.f, s1 = 0.f;
#pragma unroll
            for (int i = 0; i < 2; i++) {
                s0 += acc[i][j][0] * acc[i + 2][j][0] + acc[i][j][2] * acc[i + 2][j][2];
                s1 += acc[i][j][1] * acc[i + 2][j][1] + acc[i][j][3] * acc[i + 2][j][3];
            }
#pragma unroll
            for (int m = 4; m <= 16; m <<= 1) {
                s0 += __shfl_xor_sync(0xffffffffu, s0, m);
                s1 += __shfl_xor_sync(0xffffffffu, s1, m);
            }
            if (g == 0) {
                int p = bp * 128 + warp_n * 32 + j * 8 + 2 * q;
                *(float2*)(tb + p) = make_float2(s0 * 0.0625f, s1 * 0.0625f);
            }
        }
    } else {
        // ---- v epilogue ----
#pragma unroll
        for (int i = 0; i < 4; i++) {
            int o = (bo - 4) * 128 + warp_m * 64 + i * 16 + g;
#pragma unroll
            for (int j = 0; j < 4; j++) {
                int p = bp * 128 + warp_n * 32 + j * 8 + 2 * q;
                *(float2*)(g_v + (size_t)o * NP + p)       = make_float2(acc[i][j][0], acc[i][j][1]);
                *(float2*)(g_v + (size_t)(o + 8) * NP + p) = make_float2(acc[i][j][2], acc[i][j][3]);
            }
        }
    }
}

// ---------------------------------------------------------------------------
// Kernel 3: 3x3 regional softmax + weighted V sum, 2 output rows per block.
// grid (96, 16): block = rows {h0, h0+1}, head (y>>1), 16-ch half (y&1).
// 384 threads. Phase 1: weights for both rows (tid = r*192 + w).
// Phase 2: walk 4 input rows ONCE; each feeds the 1-2 output rows in range.
// Thread = (w-quad 0..47, ch-sub 0..7) handling channels {cl, cl+8}.
// OOB slots contribute score 0 (exp(0-m)); OOB v contributes 0.
// ---------------------------------------------------------------------------
__global__ __launch_bounds__(384, 3) void attn(float* __restrict__ out)
{
    __shared__ float w9s[2][9][192];

    const int h0   = blockIdx.x * 2;    // first output row
    const int head = blockIdx.y >> 1;   // 0..7
    const int chf  = blockIdx.y & 1;    // 0..1 channel half
    const int tid  = threadIdx.x;       // 0..383

    // ---- phase 1: softmax weights for rows h0, h0+1 ----
    {
        const int r = tid / 192;        // 0..1
        const int w = tid % 192;
        const int h = h0 + r;
        const float* tb = g_t + (size_t)head * NP;
        float sc[9];
#pragma unroll
        for (int s = 0; s < 9; s++) {
            int hh = h + s / 3 - 1;
            int ww = w + s % 3 - 1;
            float v = 0.f;
            if ((unsigned)hh < 192u && (unsigned)ww < 192u)
                v = tb[hh * WW + ww];
            sc[s] = v;
        }
        float m = sc[0];
#pragma unroll
        for (int s = 1; s < 9; s++) m = fmaxf(m, sc[s]);
        float sum = 0.f;
#pragma unroll
        for (int s = 0; s < 9; s++) { float e = __expf(sc[s] - m); sc[s] = e; sum += e; }
        float inv = 1.0f / sum;
#pragma unroll
        for (int s = 0; s < 9; s++) w9s[r][s][w] = sc[s] * inv;
    }
    __syncthreads();

    // ---- phase 2 ----
    const int qw = tid % 48;
    const int w0 = qw * 4;
    const int cl = tid / 48;                        // 0..7
    const int ch0 = head * 32 + chf * 16 + cl;      // channels ch0, ch0+8

    float o[2][2][4];
#pragma unroll
    for (int r = 0; r < 2; r++)
#pragma unroll
        for (int c = 0; c < 2; c++)
#pragma unroll
            for (int k = 0; k < 4; k++) o[r][c][k] = 0.f;

    const float* vb0 = g_v + (size_t)ch0 * NP + w0;
    const float* vb1 = vb0 + (size_t)8 * NP;

#pragma unroll
    for (int hi = 0; hi < 4; hi++) {
        const int hh = h0 - 1 + hi;
        if ((unsigned)hh >= 192u) continue;

        const float* row0 = vb0 + hh * WW;
        const float* row1 = vb1 + hh * WW;
        float4 c0 = *(const float4*)row0;
        float4 c1 = *(const float4*)row1;
        float l0 = (w0 > 0)   ? row0[-1] : 0.f;
        float r0 = (w0 < 188) ? row0[4]  : 0.f;
        float l1 = (w0 > 0)   ? row1[-1] : 0.f;
        float r1 = (w0 < 188) ? row1[4]  : 0.f;

#pragma unroll
        for (int r = 0; r < 2; r++) {
            const int dh = hi - r;                  // weight row for output h0+r
            if (dh < 0 || dh > 2) continue;
            float4 Wa = *(const float4*)&w9s[r][dh * 3 + 0][w0];
            float4 Wb = *(const float4*)&w9s[r][dh * 3 + 1][w0];
            float4 Wc = *(const float4*)&w9s[r][dh * 3 + 2][w0];

            o[r][0][0] += Wa.x * l0   + Wb.x * c0.x + Wc.x * c0.y;
            o[r][0][1] += Wa.y * c0.x + Wb.y * c0.y + Wc.y * c0.z;
            o[r][0][2] += Wa.z * c0.y + Wb.z * c0.z + Wc.z * c0.w;
            o[r][0][3] += Wa.w * c0.z + Wb.w * c0.w + Wc.w * r0;

            o[r][1][0] += Wa.x * l1   + Wb.x * c1.x + Wc.x * c1.y;
            o[r][1][1] += Wa.y * c1.x + Wb.y * c1.y + Wc.y * c1.z;
            o[r][1][2] += Wa.z * c1.y + Wb.z * c1.z + Wc.z * c1.w;
            o[r][1][3] += Wa.w * c1.z + Wb.w * c1.w + Wc.w * r1;
        }
    }

#pragma unroll
    for (int r = 0; r < 2; r++) {
        float* ob0 = out + (size_t)ch0 * NP + (h0 + r) * WW + w0;
        *(float4*)ob0 = make_float4(o[r][0][0], o[r][0][1], o[r][0][2], o[r][0][3]);
        *(float4*)(ob0 + (size_t)8 * NP) = make_float4(o[r][1][0], o[r][1][1], o[r][1][2], o[r][1][3]);
    }
}

// ---------------------------------------------------------------------------
extern "C" void kernel_launch(void* const* d_in, const int* in_sizes, int n_in,
                              void* d_out, int out_size)
{
    const float* x  = (const float*)d_in[0];
    const float* wq = (const float*)d_in[1];
    const float* wk = (const float*)d_in[2];
    const float* wv = (const float*)d_in[3];
    float* out = (float*)d_out;

    cudaFuncSetAttribute(gemm_qkv, cudaFuncAttributeMaxDynamicSharedMemorySize, 2 * STAGE);

    dim3 g1(NP / 128, 6);            // (288, 6)
    gemm_qkv<<<g1, 256, 2 * STAGE>>>(x, wq, wk, wv);

    dim3 g3(HH / 2, 16);             // (96, 16)
    attn<<<g3, 384>>>(out);
}